// round 1
// baseline (speedup 1.0000x reference)
#include <cuda_runtime.h>
#include <math.h>

#define NN 30000
#define EE 480000
#define RR 8
#define BB 4
#define HH 128
#define KTOT (BB*HH)   // 512

// ---------------- scratch (static device globals; no allocs) ----------------
__device__ int      g_counts[NN];
__device__ int      g_offsets[NN + 1];
__device__ int      g_cursor[NN];
__device__ int      g_psrc[EE];     // src | (rel<<24), permuted by dst
__device__ int      g_px[EE];       // x[src], permuted by dst
__device__ float    g_pnorm[EE];    // norm, permuted by dst
__device__ float    g_h1[NN * HH];
__device__ float    g_h2[NN * HH];
__device__ float    g_h3[NN * HH];
__device__ float    g_agg[BB][NN * HH];   // basis-aggregated neighbor sums
__device__ float    g_logits[NN];
__device__ unsigned g_maxbits;
__device__ float    g_Z;

// ordered-uint encoding for float atomicMax
__device__ __forceinline__ unsigned f2o(float f) {
    unsigned u = __float_as_uint(f);
    return (u & 0x80000000u) ? ~u : (u | 0x80000000u);
}
__device__ __forceinline__ float o2f(unsigned u) {
    return (u & 0x80000000u) ? __uint_as_float(u & 0x7fffffffu) : __uint_as_float(~u);
}

#define FMA4(A, C, V) do { (A).x += (C)*(V).x; (A).y += (C)*(V).y; (A).z += (C)*(V).z; (A).w += (C)*(V).w; } while(0)

// ---------------- init: zero counters, output, scalars ----------------
__global__ void k_init(float* out) {
    int i = blockIdx.x * blockDim.x + threadIdx.x;
    if (i < NN) g_counts[i] = 0;
    if (i < HH) out[i] = 0.0f;
    if (i == 0) { g_maxbits = f2o(-3.4e38f); g_Z = 0.0f; }
}

// ---------------- CSR build ----------------
__global__ void k_hist(const int* __restrict__ dst) {
    int e = blockIdx.x * blockDim.x + threadIdx.x;
    if (e < EE) atomicAdd(&g_counts[dst[e]], 1);
}

// single-block exclusive scan over g_counts -> g_offsets, g_cursor
__global__ void k_scan() {
    __shared__ int wsum[32];
    __shared__ int carry_s;
    int tid = threadIdx.x, lane = tid & 31, wid = tid >> 5;
    if (tid == 0) carry_s = 0;
    __syncthreads();
    int nch = (NN + 1023) >> 10;
    for (int c = 0; c < nch; c++) {
        int i = (c << 10) + tid;
        int v = (i < NN) ? g_counts[i] : 0;
        int s = v;
#pragma unroll
        for (int o = 1; o < 32; o <<= 1) { int t = __shfl_up_sync(0xffffffffu, s, o); if (lane >= o) s += t; }
        if (lane == 31) wsum[wid] = s;
        __syncthreads();
        if (wid == 0) {
            int ws = wsum[lane];
#pragma unroll
            for (int o = 1; o < 32; o <<= 1) { int t = __shfl_up_sync(0xffffffffu, ws, o); if (lane >= o) ws += t; }
            wsum[lane] = ws;
        }
        __syncthreads();
        int wprefix = wid ? wsum[wid - 1] : 0;
        int carry = carry_s;
        int excl = carry + wprefix + s - v;
        if (i < NN) { g_offsets[i] = excl; g_cursor[i] = excl; }
        int total = wsum[31];
        __syncthreads();
        if (tid == 0) carry_s = carry + total;
        __syncthreads();
    }
    if (tid == 0) g_offsets[NN] = carry_s;
}

__global__ void k_fill(const int* __restrict__ x, const int* __restrict__ src,
                       const int* __restrict__ dst, const int* __restrict__ rel,
                       const float* __restrict__ norm) {
    int e = blockIdx.x * blockDim.x + threadIdx.x;
    if (e >= EE) return;
    int d = dst[e];
    int p = atomicAdd(&g_cursor[d], 1);
    int s = src[e];
    g_psrc[p]  = s | (rel[e] << 24);
    g_px[p]    = x[s];
    g_pnorm[p] = norm[e];
}

// ---------------- layer 1: ID-feature RGC, pull (warp per dst node) ----------------
__global__ __launch_bounds__(256) void k_l1(const float* __restrict__ Vin,
                                            const float* __restrict__ comp,
                                            const float* __restrict__ bias) {
    __shared__ float sc[RR * BB];
    if (threadIdx.x < RR * BB) sc[threadIdx.x] = comp[threadIdx.x];
    __syncthreads();
    int w = (blockIdx.x * blockDim.x + threadIdx.x) >> 5;
    int lane = threadIdx.x & 31;
    if (w >= NN) return;
    int beg = g_offsets[w], end = g_offsets[w + 1];
    float4 acc = {0.f, 0.f, 0.f, 0.f};
    for (int i = beg; i < end; i++) {
        int m = g_psrc[i];
        int r = ((unsigned)m) >> 24;
        int xs = g_px[i];
        float nrm = g_pnorm[i];
        const float* cp = &sc[r * BB];
        float c0 = nrm * cp[0], c1 = nrm * cp[1], c2 = nrm * cp[2], c3 = nrm * cp[3];
        int base = xs * HH + lane * 4;
        float4 v0 = *(const float4*)&Vin[0 * NN * HH + base];
        float4 v1 = *(const float4*)&Vin[1 * NN * HH + base];
        float4 v2 = *(const float4*)&Vin[2 * NN * HH + base];
        float4 v3 = *(const float4*)&Vin[3 * NN * HH + base];
        FMA4(acc, c0, v0); FMA4(acc, c1, v1); FMA4(acc, c2, v2); FMA4(acc, c3, v3);
    }
    float4 b4 = *(const float4*)&bias[lane * 4];
    acc.x = fmaxf(acc.x + b4.x, 0.f);
    acc.y = fmaxf(acc.y + b4.y, 0.f);
    acc.z = fmaxf(acc.z + b4.z, 0.f);
    acc.w = fmaxf(acc.w + b4.w, 0.f);
    *(float4*)&g_h1[w * HH + lane * 4] = acc;
}

// ---------------- dense-layer pull: accumulate 4 basis-weighted sums ----------------
__global__ __launch_bounds__(256) void k_dense(int hsel, const float* __restrict__ comp) {
    const float* hin = hsel ? g_h2 : g_h1;
    __shared__ float sc[RR * BB];
    if (threadIdx.x < RR * BB) sc[threadIdx.x] = comp[threadIdx.x];
    __syncthreads();
    int w = (blockIdx.x * blockDim.x + threadIdx.x) >> 5;
    int lane = threadIdx.x & 31;
    if (w >= NN) return;
    int beg = g_offsets[w], end = g_offsets[w + 1];
    float4 a0 = {0.f,0.f,0.f,0.f}, a1 = a0, a2 = a0, a3 = a0;
    for (int i = beg; i < end; i++) {
        int m = g_psrc[i];
        int s = m & 0xFFFFFF;
        int r = ((unsigned)m) >> 24;
        float nrm = g_pnorm[i];
        const float* cp = &sc[r * BB];
        float c0 = nrm * cp[0], c1 = nrm * cp[1], c2 = nrm * cp[2], c3 = nrm * cp[3];
        float4 v = *(const float4*)&hin[s * HH + lane * 4];
        FMA4(a0, c0, v); FMA4(a1, c1, v); FMA4(a2, c2, v); FMA4(a3, c3, v);
    }
    int o = w * HH + lane * 4;
    *(float4*)&g_agg[0][o] = a0;
    *(float4*)&g_agg[1][o] = a1;
    *(float4*)&g_agg[2][o] = a2;
    *(float4*)&g_agg[3][o] = a3;
}

// ---------------- GEMM: out = sum_b g_agg[b] @ V[b] + bias (optional relu) -------------
// [NN, 512] @ [512, 128], fp32 with packed f32x2 FMAs.
#define BM 64
#define BKK 16
__global__ __launch_bounds__(256) void k_gemm(const float* __restrict__ V,
                                              const float* __restrict__ bias,
                                              int outsel, int do_relu) {
    __shared__ float As[BKK][BM];   // transposed A tile
    __shared__ float Bs[BKK][HH];
    float* outp = outsel ? g_h3 : g_h2;
    int tid = threadIdx.x;
    int tx = tid & 15;   // 16 col groups of 8
    int ty = tid >> 4;   // 16 row groups of 4
    int row0 = blockIdx.x * BM;

    unsigned long long acc[4][4];
#pragma unroll
    for (int i = 0; i < 4; i++)
#pragma unroll
        for (int p = 0; p < 4; p++) acc[i][p] = 0ull;

    for (int kt = 0; kt < KTOT; kt += BKK) {
        int b  = kt >> 7;
        int kk = kt & 127;
        // load A tile: 64 rows x 16 k, each thread one float4 (k-contiguous)
        {
            int r  = tid >> 2;
            int k4 = (tid & 3) * 4;
            int grow = row0 + r;
            float4 a4 = {0.f, 0.f, 0.f, 0.f};
            if (grow < NN) a4 = *(const float4*)&g_agg[b][grow * HH + kk + k4];
            As[k4 + 0][r] = a4.x; As[k4 + 1][r] = a4.y;
            As[k4 + 2][r] = a4.z; As[k4 + 3][r] = a4.w;
        }
        // load B tile: 16 k x 128 j, each thread 8 floats (j-contiguous)
        {
            int idx = tid * 8;
            int k = idx >> 7;
            int j = idx & 127;
            const float4* s4 = (const float4*)&V[(b * HH + kk + k) * HH + j];
            float4 b0 = s4[0], b1 = s4[1];
            *(float4*)&Bs[k][j]     = b0;
            *(float4*)&Bs[k][j + 4] = b1;
        }
        __syncthreads();
#pragma unroll
        for (int k = 0; k < BKK; k++) {
            unsigned long long a2[4];
#pragma unroll
            for (int i = 0; i < 4; i++) {
                float av = As[k][ty * 4 + i];
                asm("mov.b64 %0, {%1,%1};" : "=l"(a2[i]) : "f"(av));
            }
            unsigned long long b2[4];
            const unsigned long long* brow = (const unsigned long long*)&Bs[k][tx * 8];
#pragma unroll
            for (int p = 0; p < 4; p++) b2[p] = brow[p];
#pragma unroll
            for (int i = 0; i < 4; i++)
#pragma unroll
                for (int p = 0; p < 4; p++)
                    asm("fma.rn.f32x2 %0, %1, %2, %0;" : "+l"(acc[i][p]) : "l"(a2[i]), "l"(b2[p]));
        }
        __syncthreads();
    }
    // epilogue
#pragma unroll
    for (int i = 0; i < 4; i++) {
        int r = row0 + ty * 4 + i;
        if (r >= NN) continue;
        float vals[8];
#pragma unroll
        for (int p = 0; p < 4; p++) {
            float lo, hi;
            asm("mov.b64 {%0,%1}, %2;" : "=f"(lo), "=f"(hi) : "l"(acc[i][p]));
            vals[2 * p] = lo; vals[2 * p + 1] = hi;
        }
        int j0 = tx * 8;
#pragma unroll
        for (int u = 0; u < 8; u++) {
            float v = vals[u] + bias[j0 + u];
            if (do_relu) v = fmaxf(v, 0.f);
            vals[u] = v;
        }
        float4 o0 = {vals[0], vals[1], vals[2], vals[3]};
        float4 o1 = {vals[4], vals[5], vals[6], vals[7]};
        float* orow = outp + r * HH + j0;
        *(float4*)orow = o0;
        *(float4*)(orow + 4) = o1;
    }
}

// ---------------- pooling ----------------
__global__ __launch_bounds__(256) void k_logits(const float* __restrict__ gw,
                                                const float* __restrict__ gb) {
    int w = (blockIdx.x * blockDim.x + threadIdx.x) >> 5;
    int lane = threadIdx.x & 31;
    if (w >= NN) return;
    float4 h = *(const float4*)&g_h3[w * HH + lane * 4];
    float4 g = *(const float4*)&gw[lane * 4];
    float s = h.x * g.x + h.y * g.y + h.z * g.z + h.w * g.w;
#pragma unroll
    for (int o = 16; o; o >>= 1) s += __shfl_xor_sync(0xffffffffu, s, o);
    if (lane == 0) {
        float lg = s + gb[0];
        g_logits[w] = lg;
        atomicMax(&g_maxbits, f2o(lg));
    }
}

__global__ __launch_bounds__(256) void k_zsum() {
    float mx = o2f(g_maxbits);
    float s = 0.f;
    for (int i = blockIdx.x * blockDim.x + threadIdx.x; i < NN; i += gridDim.x * blockDim.x)
        s += expf(g_logits[i] - mx);
#pragma unroll
    for (int o = 16; o; o >>= 1) s += __shfl_xor_sync(0xffffffffu, s, o);
    __shared__ float ws[8];
    int lane = threadIdx.x & 31, wid = threadIdx.x >> 5;
    if (lane == 0) ws[wid] = s;
    __syncthreads();
    if (wid == 0) {
        s = (lane < 8) ? ws[lane] : 0.f;
#pragma unroll
        for (int o = 4; o; o >>= 1) s += __shfl_xor_sync(0xffffffffu, s, o);
        if (lane == 0) atomicAdd(&g_Z, s);
    }
}

__global__ void k_pool(float* __restrict__ out) {
    float mx = o2f(g_maxbits);
    float invZ = 1.0f / g_Z;
    int j = threadIdx.x;  // 128 threads
    float acc = 0.f;
    for (int n = blockIdx.x; n < NN; n += gridDim.x) {
        float wgt = expf(g_logits[n] - mx);
        acc += wgt * g_h3[n * HH + j];
    }
    atomicAdd(&out[j], acc * invZ);
}

// ---------------- launcher ----------------
extern "C" void kernel_launch(void* const* d_in, const int* in_sizes, int n_in,
                              void* d_out, int out_size) {
    const int*   x        = (const int*)d_in[0];
    const int*   src      = (const int*)d_in[1];
    const int*   dst      = (const int*)d_in[2];
    const int*   rel      = (const int*)d_in[3];
    const float* norm     = (const float*)d_in[4];
    const float* V_in     = (const float*)d_in[5];
    const float* comp_in  = (const float*)d_in[6];
    const float* bias_in  = (const float*)d_in[7];
    const float* V_h      = (const float*)d_in[8];
    const float* comp_h   = (const float*)d_in[9];
    const float* bias_h   = (const float*)d_in[10];
    const float* V_out    = (const float*)d_in[11];
    const float* comp_out = (const float*)d_in[12];
    const float* bias_out = (const float*)d_in[13];
    const float* gate_W   = (const float*)d_in[14];
    const float* gate_b   = (const float*)d_in[15];
    float* out = (float*)d_out;

    const int eblocks = (EE + 255) / 256;
    const int nwarp_blocks = (NN * 32 + 255) / 256;
    const int gemm_blocks = (NN + BM - 1) / BM;

    k_init<<<(NN + 255) / 256, 256>>>(out);
    k_hist<<<eblocks, 256>>>(dst);
    k_scan<<<1, 1024>>>();
    k_fill<<<eblocks, 256>>>(x, src, dst, rel, norm);
    k_l1<<<nwarp_blocks, 256>>>(V_in, comp_in, bias_in);
    k_dense<<<nwarp_blocks, 256>>>(0, comp_h);
    k_gemm<<<gemm_blocks, 256>>>(V_h, bias_h, 0, 1);
    k_dense<<<nwarp_blocks, 256>>>(1, comp_out);
    k_gemm<<<gemm_blocks, 256>>>(V_out, bias_out, 1, 0);
    k_logits<<<nwarp_blocks, 256>>>(gate_W, gate_b);
    k_zsum<<<64, 256>>>();
    k_pool<<<128, 128>>>(out);
}

// round 3
// speedup vs baseline: 1.7772x; 1.7772x over previous
#include <cuda_runtime.h>
#include <math.h>
#include <stdint.h>

#define NN 30000
#define EE 480000
#define RR 8
#define BB 4
#define HH 128
#define KTOT (BB*HH)   // 512

// ---------------- scratch (static device globals; no allocs) ----------------
__device__ int      g_counts[NN];
__device__ int      g_offsets[NN + 1];
__device__ int      g_cursor[NN];
__device__ int4     g_edge[EE];          // {src|(rel<<24), x[src], norm bits, 0} permuted by dst
__device__ float    g_h1[NN * HH];
__device__ float    g_h2[NN * HH];
__device__ float    g_h3[NN * HH];
__device__ float    g_agg[BB][NN * HH];  // basis-aggregated neighbor sums
__device__ float    g_Bt[2][HH * KTOT];  // transposed weights, [n][k], tf32-rounded
__device__ float    g_logits[NN];
__device__ unsigned g_maxbits;
__device__ float    g_Z;

// ordered-uint encoding for float atomicMax
__device__ __forceinline__ unsigned f2o(float f) {
    unsigned u = __float_as_uint(f);
    return (u & 0x80000000u) ? ~u : (u | 0x80000000u);
}
__device__ __forceinline__ float o2f(unsigned u) {
    return (u & 0x80000000u) ? __uint_as_float(u & 0x7fffffffu) : __uint_as_float(~u);
}

__device__ __forceinline__ float to_tf32(float x) {
    float r; asm("cvt.rna.tf32.f32 %0, %1;" : "=f"(r) : "f"(x)); return r;
}

#define FMA4(A, C, V) do { (A).x += (C)*(V).x; (A).y += (C)*(V).y; (A).z += (C)*(V).z; (A).w += (C)*(V).w; } while(0)

// ---------------- init ----------------
__global__ void k_init(float* out) {
    int i = blockIdx.x * blockDim.x + threadIdx.x;
    if (i < NN) g_counts[i] = 0;
    if (i < HH) out[i] = 0.0f;
    if (i == 0) { g_maxbits = f2o(-3.4e38f); g_Z = 0.0f; }
}

// ---------------- CSR build ----------------
__global__ void k_hist(const int* __restrict__ dst) {
    int e = blockIdx.x * blockDim.x + threadIdx.x;
    if (e < EE) atomicAdd(&g_counts[dst[e]], 1);
}

__global__ void k_scan() {
    __shared__ int wsum[32];
    __shared__ int carry_s;
    int tid = threadIdx.x, lane = tid & 31, wid = tid >> 5;
    if (tid == 0) carry_s = 0;
    __syncthreads();
    int nch = (NN + 1023) >> 10;
    for (int c = 0; c < nch; c++) {
        int i = (c << 10) + tid;
        int v = (i < NN) ? g_counts[i] : 0;
        int s = v;
#pragma unroll
        for (int o = 1; o < 32; o <<= 1) { int t = __shfl_up_sync(0xffffffffu, s, o); if (lane >= o) s += t; }
        if (lane == 31) wsum[wid] = s;
        __syncthreads();
        if (wid == 0) {
            int ws = wsum[lane];
#pragma unroll
            for (int o = 1; o < 32; o <<= 1) { int t = __shfl_up_sync(0xffffffffu, ws, o); if (lane >= o) ws += t; }
            wsum[lane] = ws;
        }
        __syncthreads();
        int wprefix = wid ? wsum[wid - 1] : 0;
        int carry = carry_s;
        int excl = carry + wprefix + s - v;
        if (i < NN) { g_offsets[i] = excl; g_cursor[i] = excl; }
        int total = wsum[31];
        __syncthreads();
        if (tid == 0) carry_s = carry + total;
        __syncthreads();
    }
    if (tid == 0) g_offsets[NN] = carry_s;
}

__global__ void k_fill(const int* __restrict__ x, const int* __restrict__ src,
                       const int* __restrict__ dst, const int* __restrict__ rel,
                       const float* __restrict__ norm) {
    int e = blockIdx.x * blockDim.x + threadIdx.x;
    if (e >= EE) return;
    int d = dst[e];
    int p = atomicAdd(&g_cursor[d], 1);
    int s = src[e];
    int4 ed;
    ed.x = s | (rel[e] << 24);
    ed.y = x[s];
    ed.z = __float_as_int(norm[e]);
    ed.w = 0;
    g_edge[p] = ed;
}

// ---------------- transpose V into [N, K] K-major (tf32-rounded) ----------------
__global__ void k_transpose(const float* __restrict__ Vh, const float* __restrict__ Vo) {
    int i = blockIdx.x * blockDim.x + threadIdx.x;
    if (i >= BB * HH * HH) return;
    // output-coalesced: i = n*512 + b*128 + kk
    int n = i >> 9;
    int rem = i & 511;
    int b = rem >> 7;
    int kk = rem & 127;
    int s = (b * HH + kk) * HH + n;
    g_Bt[0][i] = to_tf32(Vh[s]);
    g_Bt[1][i] = to_tf32(Vo[s]);
}

// ---------------- layer 1: ID-feature RGC, pull (warp per dst node) ----------------
__global__ __launch_bounds__(256) void k_l1(const float* __restrict__ Vin,
                                            const float* __restrict__ comp,
                                            const float* __restrict__ bias) {
    __shared__ float sc[RR * BB];
    if (threadIdx.x < RR * BB) sc[threadIdx.x] = comp[threadIdx.x];
    __syncthreads();
    int w = (blockIdx.x * blockDim.x + threadIdx.x) >> 5;
    int lane = threadIdx.x & 31;
    if (w >= NN) return;
    int beg = g_offsets[w], end = g_offsets[w + 1];
    float4 acc = {0.f, 0.f, 0.f, 0.f};
#pragma unroll 2
    for (int i = beg; i < end; i++) {
        int4 ed = g_edge[i];
        int r = ((unsigned)ed.x) >> 24;
        int xs = ed.y;
        float nrm = __int_as_float(ed.z);
        const float* cp = &sc[r * BB];
        float c0 = nrm * cp[0], c1 = nrm * cp[1], c2 = nrm * cp[2], c3 = nrm * cp[3];
        int base = xs * HH + lane * 4;
        float4 v0 = *(const float4*)&Vin[0 * NN * HH + base];
        float4 v1 = *(const float4*)&Vin[1 * NN * HH + base];
        float4 v2 = *(const float4*)&Vin[2 * NN * HH + base];
        float4 v3 = *(const float4*)&Vin[3 * NN * HH + base];
        FMA4(acc, c0, v0); FMA4(acc, c1, v1); FMA4(acc, c2, v2); FMA4(acc, c3, v3);
    }
    float4 b4 = *(const float4*)&bias[lane * 4];
    acc.x = fmaxf(acc.x + b4.x, 0.f);
    acc.y = fmaxf(acc.y + b4.y, 0.f);
    acc.z = fmaxf(acc.z + b4.z, 0.f);
    acc.w = fmaxf(acc.w + b4.w, 0.f);
    *(float4*)&g_h1[w * HH + lane * 4] = acc;
}

// ---------------- dense-layer pull: accumulate 4 basis-weighted sums ----------------
__global__ __launch_bounds__(256) void k_dense(int hsel, const float* __restrict__ comp) {
    const float* hin = hsel ? g_h2 : g_h1;
    __shared__ float sc[RR * BB];
    if (threadIdx.x < RR * BB) sc[threadIdx.x] = comp[threadIdx.x];
    __syncthreads();
    int w = (blockIdx.x * blockDim.x + threadIdx.x) >> 5;
    int lane = threadIdx.x & 31;
    if (w >= NN) return;
    int beg = g_offsets[w], end = g_offsets[w + 1];
    float4 a0 = {0.f,0.f,0.f,0.f}, a1 = a0, a2 = a0, a3 = a0;
#pragma unroll 2
    for (int i = beg; i < end; i++) {
        int4 ed = g_edge[i];
        int s = ed.x & 0xFFFFFF;
        int r = ((unsigned)ed.x) >> 24;
        float nrm = __int_as_float(ed.z);
        const float* cp = &sc[r * BB];
        float c0 = nrm * cp[0], c1 = nrm * cp[1], c2 = nrm * cp[2], c3 = nrm * cp[3];
        float4 v = *(const float4*)&hin[s * HH + lane * 4];
        FMA4(a0, c0, v); FMA4(a1, c1, v); FMA4(a2, c2, v); FMA4(a3, c3, v);
    }
    int o = w * HH + lane * 4;
    *(float4*)&g_agg[0][o] = a0;
    *(float4*)&g_agg[1][o] = a1;
    *(float4*)&g_agg[2][o] = a2;
    *(float4*)&g_agg[3][o] = a3;
}

// ---------------- mma.sync tf32 GEMM: out = [sum_b agg_b @ V_b] + bias ----------------
// C[NN,128] = A[NN,512] @ B[512,128]. CTA tile 128x128, K chunked by 64.
// 8 warps: warp_m = wid&3 (32 rows each), warp_n = wid>>2 (64 cols each).
// Smem rows padded to 68 floats -> conflict-free fragment loads.
#define GM 128
#define GKC 64
#define ASTRIDE 68
#define SMEM_GEMM (2 * GM * ASTRIDE * 4)

__global__ __launch_bounds__(256) void k_gemm_mma(int layer, const float* __restrict__ bias,
                                                  int outsel, int do_relu) {
    extern __shared__ float sm[];
    float* As = sm;                       // [128][68]
    float* Bs = sm + GM * ASTRIDE;        // [128][68]
    float* outp = outsel ? g_h3 : g_h2;
    const float* Bt = g_Bt[layer];

    int tid = threadIdx.x;
    int lane = tid & 31, wid = tid >> 5;
    int warp_m = wid & 3, warp_n = wid >> 2;
    int gid = lane >> 2;     // groupID (0..7)
    int tig = lane & 3;      // thread in group
    int row0 = blockIdx.x * GM;

    float acc[2][8][4];
#pragma unroll
    for (int t = 0; t < 2; t++)
#pragma unroll
        for (int nt = 0; nt < 8; nt++)
#pragma unroll
            for (int q = 0; q < 4; q++) acc[t][nt][q] = 0.f;

    for (int c = 0; c < KTOT / GKC; c++) {
        const float* Asrc = g_agg[c >> 1];
        int kk0 = (c & 1) * GKC;
#pragma unroll
        for (int i = 0; i < 8; i++) {
            int linear = tid + 256 * i;      // 0..2047
            int r = linear >> 4;             // 0..127
            int k4 = (linear & 15) * 4;      // 0..60
            float4 av = {0.f, 0.f, 0.f, 0.f};
            int grow = row0 + r;
            if (grow < NN) av = *(const float4*)&Asrc[grow * HH + kk0 + k4];
            float* da = &As[r * ASTRIDE + k4];
            da[0] = to_tf32(av.x); da[1] = to_tf32(av.y);
            da[2] = to_tf32(av.z); da[3] = to_tf32(av.w);
            float4 bv = *(const float4*)&Bt[r * KTOT + c * GKC + k4];
            float* db = &Bs[r * ASTRIDE + k4];
            db[0] = bv.x; db[1] = bv.y; db[2] = bv.z; db[3] = bv.w;
        }
        __syncthreads();
#pragma unroll
        for (int ks = 0; ks < GKC / 8; ks++) {
            int kb = ks * 8;
            uint32_t a[2][4];
#pragma unroll
            for (int t = 0; t < 2; t++) {
                int m = warp_m * 32 + t * 16 + gid;
                const float* ap0 = &As[m * ASTRIDE + kb + tig];
                const float* ap1 = &As[(m + 8) * ASTRIDE + kb + tig];
                a[t][0] = __float_as_uint(ap0[0]);
                a[t][1] = __float_as_uint(ap1[0]);
                a[t][2] = __float_as_uint(ap0[4]);
                a[t][3] = __float_as_uint(ap1[4]);
            }
#pragma unroll
            for (int nt = 0; nt < 8; nt++) {
                int n = warp_n * 64 + nt * 8 + gid;
                const float* bp = &Bs[n * ASTRIDE + kb + tig];
                uint32_t b0 = __float_as_uint(bp[0]);
                uint32_t b1 = __float_as_uint(bp[4]);
#pragma unroll
                for (int t = 0; t < 2; t++) {
                    asm volatile(
                        "mma.sync.aligned.m16n8k8.row.col.f32.tf32.tf32.f32 "
                        "{%0,%1,%2,%3}, {%4,%5,%6,%7}, {%8,%9}, {%0,%1,%2,%3};"
                        : "+f"(acc[t][nt][0]), "+f"(acc[t][nt][1]),
                          "+f"(acc[t][nt][2]), "+f"(acc[t][nt][3])
                        : "r"(a[t][0]), "r"(a[t][1]), "r"(a[t][2]), "r"(a[t][3]),
                          "r"(b0), "r"(b1));
                }
            }
        }
        __syncthreads();
    }

    // epilogue: c0,c1 at (row, col..col+1); c2,c3 at (row+8, col..col+1)
#pragma unroll
    for (int t = 0; t < 2; t++) {
#pragma unroll
        for (int nt = 0; nt < 8; nt++) {
            int col = warp_n * 64 + nt * 8 + tig * 2;
            float bx = bias[col], by = bias[col + 1];
            int r0 = row0 + warp_m * 32 + t * 16 + gid;
            if (r0 < NN) {
                float vx = acc[t][nt][0] + bx;
                float vy = acc[t][nt][1] + by;
                if (do_relu) { vx = fmaxf(vx, 0.f); vy = fmaxf(vy, 0.f); }
                float2 v = {vx, vy};
                *(float2*)&outp[r0 * HH + col] = v;
            }
            int r1 = r0 + 8;
            if (r1 < NN) {
                float vx = acc[t][nt][2] + bx;
                float vy = acc[t][nt][3] + by;
                if (do_relu) { vx = fmaxf(vx, 0.f); vy = fmaxf(vy, 0.f); }
                float2 v = {vx, vy};
                *(float2*)&outp[r1 * HH + col] = v;
            }
        }
    }
}

// ---------------- pooling ----------------
__global__ __launch_bounds__(256) void k_logits(const float* __restrict__ gw,
                                                const float* __restrict__ gb) {
    int w = (blockIdx.x * blockDim.x + threadIdx.x) >> 5;
    int lane = threadIdx.x & 31;
    if (w >= NN) return;
    float4 h = *(const float4*)&g_h3[w * HH + lane * 4];
    float4 g = *(const float4*)&gw[lane * 4];
    float s = h.x * g.x + h.y * g.y + h.z * g.z + h.w * g.w;
#pragma unroll
    for (int o = 16; o; o >>= 1) s += __shfl_xor_sync(0xffffffffu, s, o);
    if (lane == 0) {
        float lg = s + gb[0];
        g_logits[w] = lg;
        atomicMax(&g_maxbits, f2o(lg));
    }
}

__global__ __launch_bounds__(256) void k_zsum() {
    float mx = o2f(g_maxbits);
    float s = 0.f;
    for (int i = blockIdx.x * blockDim.x + threadIdx.x; i < NN; i += gridDim.x * blockDim.x)
        s += expf(g_logits[i] - mx);
#pragma unroll
    for (int o = 16; o; o >>= 1) s += __shfl_xor_sync(0xffffffffu, s, o);
    __shared__ float ws[8];
    int lane = threadIdx.x & 31, wid = threadIdx.x >> 5;
    if (lane == 0) ws[wid] = s;
    __syncthreads();
    if (wid == 0) {
        s = (lane < 8) ? ws[lane] : 0.f;
#pragma unroll
        for (int o = 4; o; o >>= 1) s += __shfl_xor_sync(0xffffffffu, s, o);
        if (lane == 0) atomicAdd(&g_Z, s);
    }
}

__global__ void k_pool(float* __restrict__ out) {
    float mx = o2f(g_maxbits);
    float invZ = 1.0f / g_Z;
    int j = threadIdx.x;  // 128 threads
    float acc = 0.f;
    for (int n = blockIdx.x; n < NN; n += gridDim.x) {
        float wgt = expf(g_logits[n] - mx);
        acc += wgt * g_h3[n * HH + j];
    }
    atomicAdd(&out[j], acc * invZ);
}

// ---------------- launcher ----------------
extern "C" void kernel_launch(void* const* d_in, const int* in_sizes, int n_in,
                              void* d_out, int out_size) {
    const int*   x        = (const int*)d_in[0];
    const int*   src      = (const int*)d_in[1];
    const int*   dst      = (const int*)d_in[2];
    const int*   rel      = (const int*)d_in[3];
    const float* norm     = (const float*)d_in[4];
    const float* V_in     = (const float*)d_in[5];
    const float* comp_in  = (const float*)d_in[6];
    const float* bias_in  = (const float*)d_in[7];
    const float* V_h      = (const float*)d_in[8];
    const float* comp_h   = (const float*)d_in[9];
    const float* bias_h   = (const float*)d_in[10];
    const float* V_out    = (const float*)d_in[11];
    const float* comp_out = (const float*)d_in[12];
    const float* bias_out = (const float*)d_in[13];
    const float* gate_W   = (const float*)d_in[14];
    const float* gate_b   = (const float*)d_in[15];
    float* out = (float*)d_out;

    cudaFuncSetAttribute(k_gemm_mma, cudaFuncAttributeMaxDynamicSharedMemorySize, SMEM_GEMM);

    const int eblocks = (EE + 255) / 256;
    const int nwarp_blocks = (NN * 32 + 255) / 256;
    const int gemm_blocks = (NN + GM - 1) / GM;

    k_init<<<(NN + 255) / 256, 256>>>(out);
    k_hist<<<eblocks, 256>>>(dst);
    k_scan<<<1, 1024>>>();
    k_fill<<<eblocks, 256>>>(x, src, dst, rel, norm);
    k_transpose<<<(BB * HH * HH + 255) / 256, 256>>>(V_h, V_out);
    k_l1<<<nwarp_blocks, 256>>>(V_in, comp_in, bias_in);
    k_dense<<<nwarp_blocks, 256>>>(0, comp_h);
    k_gemm_mma<<<gemm_blocks, 256, SMEM_GEMM>>>(0, bias_h, 0, 1);
    k_dense<<<nwarp_blocks, 256>>>(1, comp_out);
    k_gemm_mma<<<gemm_blocks, 256, SMEM_GEMM>>>(1, bias_out, 1, 0);
    k_logits<<<nwarp_blocks, 256>>>(gate_W, gate_b);
    k_zsum<<<64, 256>>>();
    k_pool<<<128, 128>>>(out);
}